// round 1
// baseline (speedup 1.0000x reference)
#include <cuda_runtime.h>
#include <stdint.h>

// Problem constants (fixed shapes)
#define Bb 4
#define Cc 3
#define Hh 32
#define Ww 32
#define Dd 32
#define KK 32
#define OHh 30
#define OWw 30
#define ODd 30

// tile: [c(3)][kh(3)][dw(4)][d(32)] = 1152 floats, plus shifted copy (1152)
#define TILE_N 1152
#define SM_N   (2*TILE_N + 64)   // pad for inactive-lane overreads

__device__ float4 g_coef[KK * 31];   // (c0, ca, cb, cab) per (k, node)
__device__ int2   g_off[KK * 16];    // precomputed tile offsets per (k, leaf): .x = child a (r=0), .y = child b (r=1)

// ---------------- prep kernel: softmax -> LUT coefficients, coords -> tile offsets ----------------
__global__ void prep_kernel(const int* __restrict__ kc,
                            const float* __restrict__ w0, const float* __restrict__ w1,
                            const float* __restrict__ w2, const float* __restrict__ w3,
                            const float* __restrict__ w4) {
    int i = blockIdx.x * blockDim.x + threadIdx.x;
    if (i < KK * 31) {
        int k = i / 31, n = i % 31;
        const float* w; int node;
        if (n < 16)      { w = w0; node = n; }
        else if (n < 24) { w = w1; node = n - 16; }
        else if (n < 28) { w = w2; node = n - 24; }
        else if (n < 30) { w = w3; node = n - 28; }
        else             { w = w4; node = 0; }
        const float* p = w + (node * KK + k) * 16;
        float m = p[0];
#pragma unroll
        for (int g = 1; g < 16; ++g) m = fmaxf(m, p[g]);
        float e[16]; float s = 0.f;
#pragma unroll
        for (int g = 0; g < 16; ++g) { e[g] = expf(p[g] - m); s += e[g]; }
        float inv = 1.f / s;
        float l0 = 0.f, l1 = 0.f, l2 = 0.f, l3 = 0.f;
#pragma unroll
        for (int g = 0; g < 16; ++g) {
            float pg = e[g] * inv;
            if (g & 1) l0 += pg;   // GATES[g][0] = bit0
            if (g & 2) l1 += pg;
            if (g & 4) l2 += pg;
            if (g & 8) l3 += pg;
        }
        // val = c0 + ca*a + cb*b + cab*a*b
        g_coef[k * 31 + n] = make_float4(l0, l2 - l0, l1 - l0, l3 - l2 - l1 + l0);
    }
    if (i < KK * 16) {
        int k = i / 16, s = i % 16;
        int2 o;
#pragma unroll
        for (int r = 0; r < 2; ++r) {
            const int* c4 = kc + (((r * KK + k) * 16 + s) << 2);
            int hh = c4[0], ww = c4[1], dd = c4[2], cc = c4[3];   // coords (h,w,d,c), all in [0,3)
            int B0 = ((cc * 3 + hh) * 4 + ww) * 32;
            int off = (dd == 1) ? (TILE_N + B0) : (B0 + dd);      // kd==1 -> shifted copy (keeps 8B alignment)
            if (r == 0) o.x = off; else o.y = off;
        }
        g_off[k * 16 + s] = o;
    }
}

// ---------------- packed f32x2 helpers ----------------
__device__ __forceinline__ unsigned long long fma2(unsigned long long a, unsigned long long b,
                                                   unsigned long long c) {
    unsigned long long d;
    asm("fma.rn.f32x2 %0, %1, %2, %3;" : "=l"(d) : "l"(a), "l"(b), "l"(c));
    return d;
}
__device__ __forceinline__ unsigned long long pack2(float x) {
    unsigned long long d;
    asm("mov.b64 %0, {%1, %1};" : "=l"(d) : "f"(x));
    return d;
}

template <int N>
__device__ __forceinline__ void reduce_level(unsigned long long* acc, const float4* __restrict__ cf) {
#pragma unroll
    for (int j = 0; j < N; ++j) {
        float4 c = cf[j];
        unsigned long long A = acc[2 * j], B = acc[2 * j + 1];
        unsigned long long t = fma2(pack2(c.w), B, pack2(c.y));
        unsigned long long u = fma2(pack2(c.z), B, pack2(c.x));
        acc[j] = fma2(A, t, u);
    }
}

// ---------------- main kernel ----------------
// grid: (15, 30, 4) = (ow-pair, oh, b); block: 256 threads (8 warps)
// warp: lanes 0-14 -> row ow0 (od pairs), lanes 16-30 -> row ow0+1; each warp loops over 4 k values.
__global__ void __launch_bounds__(256) logic_kernel(const float* __restrict__ x,
                                                    float* __restrict__ out) {
    __shared__ float   sm[SM_N];
    __shared__ float4  scoef[KK * 31];
    __shared__ int2    soff[KK * 16];

    const int tid = threadIdx.x;
    const int owp = blockIdx.x;
    const int oh  = blockIdx.y;
    const int bz  = blockIdx.z;
    const int ow0 = owp * 2;

    const float* xb = x + bz * (Cc * Hh * Ww * Dd);

    // Stage tile + shifted copy. tile[i], i = ((c*3+kh)*4+dw)*32 + d
    for (int i = tid; i < TILE_N; i += 256) {
        int d  = i & 31;
        int dw = (i >> 5) & 3;
        int rr = i >> 7;               // c*3 + kh, 0..8
        int c  = rr / 3;
        int kh = rr - c * 3;
        float v = xb[((c * Hh + (oh + kh)) * Ww + (ow0 + dw)) * Dd + d];
        sm[i] = v;
        if (i >= 1) sm[TILE_N - 1 + i] = v;   // shift[i-1] = tile[i]
    }
    if (tid == 0) sm[2 * TILE_N - 1] = 0.f;
    for (int i = tid; i < SM_N - 2 * TILE_N; i += 256) sm[2 * TILE_N + i] = 0.f; // pad
    for (int i = tid; i < KK * 31; i += 256) scoef[i] = g_coef[i];
    for (int i = tid; i < KK * 16; i += 256) soff[i] = g_off[i];
    __syncthreads();

    const int w  = tid >> 5;
    const int l  = tid & 31;
    const int lr = l >> 4;          // which ow row within the pair
    const int li = l & 15;          // od-pair index (0..14 valid)
    const int lanebase = lr * 32 + 2 * li;

#pragma unroll 1
    for (int kk = 0; kk < 4; ++kk) {
        const int k = (kk << 3) + w;
        const float4* cf = scoef + k * 31;
        const int2*   of = soff + k * 16;

        unsigned long long acc[16];
#pragma unroll
        for (int s = 0; s < 16; ++s) {
            int2 o   = of[s];
            float4 c = cf[s];
            unsigned long long a  = *reinterpret_cast<const unsigned long long*>(sm + o.x + lanebase);
            unsigned long long bb = *reinterpret_cast<const unsigned long long*>(sm + o.y + lanebase);
            unsigned long long t = fma2(pack2(c.w), bb, pack2(c.y));
            unsigned long long u = fma2(pack2(c.z), bb, pack2(c.x));
            acc[s] = fma2(a, t, u);
        }
        reduce_level<8>(acc, cf + 16);
        reduce_level<4>(acc, cf + 24);
        reduce_level<2>(acc, cf + 28);
        reduce_level<1>(acc, cf + 30);

        if (li < 15) {
            int orow = (((bz * KK + k) * OHh + oh) * OWw + (ow0 + lr));
            *reinterpret_cast<float2*>(out + orow * ODd + 2 * li) =
                *reinterpret_cast<float2*>(&acc[0]);
        }
    }
}

// ---------------- launch ----------------
extern "C" void kernel_launch(void* const* d_in, const int* in_sizes, int n_in,
                              void* d_out, int out_size) {
    const float* x  = (const float*)d_in[0];
    const int*   kc = (const int*)d_in[1];
    const float* w0 = (const float*)d_in[2];
    const float* w1 = (const float*)d_in[3];
    const float* w2 = (const float*)d_in[4];
    const float* w3 = (const float*)d_in[5];
    const float* w4 = (const float*)d_in[6];
    float* out = (float*)d_out;

    prep_kernel<<<8, 128>>>(kc, w0, w1, w2, w3, w4);
    dim3 grid(OWw / 2, OHh, Bb);
    logic_kernel<<<grid, 256>>>(x, out);
}

// round 2
// speedup vs baseline: 1.1304x; 1.1304x over previous
#include <cuda_runtime.h>
#include <stdint.h>

// Problem constants (fixed shapes)
#define Bb 4
#define Cc 3
#define Hh 32
#define Ww 32
#define Dd 32
#define KK 32
#define OHh 30
#define OWw 30
#define ODd 30

// tile: [c(3)][kh(3)][dw(6)][d(32)] = 1728 floats; 3 copies shifted by 0/1/2 floats
#define TILE_N 1728
#define SM_N   (3*TILE_N)      // 5184 floats; max read index = 5183 exactly

__device__ float4 g_coef[KK * 31];   // (c0, ca, cb, cab) per (k, node)
__device__ int2   g_off[KK * 16];    // per (k, leaf): .x = child a offset, .y = child b offset (floats)

// ---------------- prep kernel ----------------
__global__ void prep_kernel(const int* __restrict__ kc,
                            const float* __restrict__ w0, const float* __restrict__ w1,
                            const float* __restrict__ w2, const float* __restrict__ w3,
                            const float* __restrict__ w4) {
    int i = blockIdx.x * blockDim.x + threadIdx.x;
    if (i < KK * 31) {
        int k = i / 31, n = i % 31;
        const float* w; int node;
        if (n < 16)      { w = w0; node = n; }
        else if (n < 24) { w = w1; node = n - 16; }
        else if (n < 28) { w = w2; node = n - 24; }
        else if (n < 30) { w = w3; node = n - 28; }
        else             { w = w4; node = 0; }
        const float* p = w + (node * KK + k) * 16;
        float m = p[0];
#pragma unroll
        for (int g = 1; g < 16; ++g) m = fmaxf(m, p[g]);
        float e[16]; float s = 0.f;
#pragma unroll
        for (int g = 0; g < 16; ++g) { e[g] = expf(p[g] - m); s += e[g]; }
        float inv = 1.f / s;
        float l0 = 0.f, l1 = 0.f, l2 = 0.f, l3 = 0.f;
#pragma unroll
        for (int g = 0; g < 16; ++g) {
            float pg = e[g] * inv;
            if (g & 1) l0 += pg;
            if (g & 2) l1 += pg;
            if (g & 4) l2 += pg;
            if (g & 8) l3 += pg;
        }
        // val = c0 + ca*a + cb*b + cab*a*b
        g_coef[k * 31 + n] = make_float4(l0, l2 - l0, l1 - l0, l3 - l2 - l1 + l0);
    }
    if (i < KK * 16) {
        int k = i / 16, s = i % 16;
        int2 o;
#pragma unroll
        for (int r = 0; r < 2; ++r) {
            const int* c4 = kc + (((r * KK + k) * 16 + s) << 2);
            int hh = c4[0], ww = c4[1], dd = c4[2], cc = c4[3];   // coords (h,w,d,c), all in [0,3)
            int B0 = ((cc * 3 + hh) * 6 + ww) * 32;
            int off = dd * TILE_N + B0;      // copy #dd starts at dd*TILE_N; copy_dd[j] = tile[j+dd]
            if (r == 0) o.x = off; else o.y = off;
        }
        g_off[k * 16 + s] = o;
    }
}

// ---------------- packed f32x2 helpers ----------------
typedef unsigned long long u64;

__device__ __forceinline__ u64 fma2(u64 a, u64 b, u64 c) {
    u64 d;
    asm("fma.rn.f32x2 %0, %1, %2, %3;" : "=l"(d) : "l"(a), "l"(b), "l"(c));
    return d;
}
__device__ __forceinline__ u64 pack2(float x) {
    u64 d;
    asm("mov.b64 %0, {%1, %1};" : "=l"(d) : "f"(x));
    return d;
}

struct V2 { u64 lo, hi; };   // 4 fp32 values (4 consecutive od)

// level bases in the coef array: L1->16, L2->24, L3->28, L4->30
template <int L> struct LvlBase { static constexpr int v = 32 - (32 >> L); };

template <int L, int J>
__device__ __forceinline__ V2 eval_node(const float* __restrict__ sm,
                                        const int2* __restrict__ of,
                                        const float4* __restrict__ cf,
                                        int lanebase) {
    if constexpr (L == 0) {
        int2 o = of[J];
        float4 c = cf[J];
        ulonglong2 a = *reinterpret_cast<const ulonglong2*>(sm + o.x + lanebase);
        ulonglong2 b = *reinterpret_cast<const ulonglong2*>(sm + o.y + lanebase);
        u64 c0 = pack2(c.x), ca = pack2(c.y), cb = pack2(c.z), cab = pack2(c.w);
        V2 r;
        r.lo = fma2(a.x, fma2(cab, b.x, ca), fma2(cb, b.x, c0));
        r.hi = fma2(a.y, fma2(cab, b.y, ca), fma2(cb, b.y, c0));
        return r;
    } else {
        V2 a = eval_node<L - 1, 2 * J>(sm, of, cf, lanebase);
        V2 b = eval_node<L - 1, 2 * J + 1>(sm, of, cf, lanebase);
        float4 c = cf[LvlBase<L>::v + J];
        u64 c0 = pack2(c.x), ca = pack2(c.y), cb = pack2(c.z), cab = pack2(c.w);
        V2 r;
        r.lo = fma2(a.lo, fma2(cab, b.lo, ca), fma2(cb, b.lo, c0));
        r.hi = fma2(a.hi, fma2(cab, b.hi, ca), fma2(cb, b.hi, c0));
        return r;
    }
}

// ---------------- main kernel ----------------
// grid: (8 ow-groups, 30 oh, 4 b); block 256 (8 warps)
// lane: row = l>>3 (4 ow rows), q = l&7 (od quad, od = 4q..4q+3; q==7 -> od 28,29 valid only)
// warp w handles k = {w, w+8, w+16, w+24}
__global__ void __launch_bounds__(256) logic_kernel(const float* __restrict__ x,
                                                    float* __restrict__ out) {
    __shared__ float   sm[SM_N];
    __shared__ float4  scoef[KK * 31];
    __shared__ int2    soff[KK * 16];

    const int tid = threadIdx.x;
    const int bg  = blockIdx.x;       // ow group (4 rows)
    const int oh  = blockIdx.y;
    const int bz  = blockIdx.z;
    const int ow0 = bg * 4;

    const float* xb = x + bz * (Cc * Hh * Ww * Dd);

    // Stage tile + 2 shifted copies. tile[i], i = ((c*3+kh)*6+dw)*32 + d
    for (int i = tid; i < TILE_N; i += 256) {
        int rr  = i / 192;            // c*3+kh, 0..8
        int rem = i - rr * 192;
        int dw  = rem >> 5;
        int d   = rem & 31;
        int c   = rr / 3;
        int kh  = rr - c * 3;
        int w_in = ow0 + dw; if (w_in > 31) w_in = 31;   // clamp (masked rows only)
        float v = xb[((c * Hh + (oh + kh)) * Ww + w_in) * Dd + d];
        sm[i] = v;
        if (i >= 1) sm[TILE_N - 1 + i] = v;       // copy1[i-1] = tile[i]
        if (i >= 2) sm[2 * TILE_N - 2 + i] = v;   // copy2[i-2] = tile[i]
    }
    if (tid == 0) { sm[2 * TILE_N - 1] = 0.f; sm[3 * TILE_N - 2] = 0.f; sm[3 * TILE_N - 1] = 0.f; }
    for (int i = tid; i < KK * 31; i += 256) scoef[i] = g_coef[i];
    for (int i = tid; i < KK * 16; i += 256) soff[i] = g_off[i];
    __syncthreads();

    const int w   = tid >> 5;
    const int l   = tid & 31;
    const int row = l >> 3;           // 0..3
    const int q   = l & 7;            // od quad
    const int lanebase = row * 32 + 4 * q;
    const int ow  = ow0 + row;
    const bool rv = (ow < OWw);

#pragma unroll 1
    for (int kk = 0; kk < 4; ++kk) {
        const int k = (kk << 3) + w;
        const float4* cf = scoef + k * 31;
        const int2*   of = soff + k * 16;

        V2 r = eval_node<4, 0>(sm, of, cf, lanebase);

        if (rv) {
            int base = (((bz * KK + k) * OHh + oh) * OWw + ow) * ODd + 4 * q;
            *reinterpret_cast<float2*>(out + base) = *reinterpret_cast<float2*>(&r.lo);
            if (q < 7)
                *reinterpret_cast<float2*>(out + base + 2) = *reinterpret_cast<float2*>(&r.hi);
        }
    }
}

// ---------------- launch ----------------
extern "C" void kernel_launch(void* const* d_in, const int* in_sizes, int n_in,
                              void* d_out, int out_size) {
    const float* x  = (const float*)d_in[0];
    const int*   kc = (const int*)d_in[1];
    const float* w0 = (const float*)d_in[2];
    const float* w1 = (const float*)d_in[3];
    const float* w2 = (const float*)d_in[4];
    const float* w3 = (const float*)d_in[5];
    const float* w4 = (const float*)d_in[6];
    float* out = (float*)d_out;

    prep_kernel<<<8, 128>>>(kc, w0, w1, w2, w3, w4);
    dim3 grid((OWw + 3) / 4, OHh, Bb);
    logic_kernel<<<grid, 256>>>(x, out);
}